// round 2
// baseline (speedup 1.0000x reference)
#include <cuda_runtime.h>
#include <cuda_bf16.h>

#define G_SIZE 4096
#define B_SIZE 16
#define NCH 15
#define LCHUNK 512
#define BLOCK 128
#define MTILE 256  // BLOCK * 2 columns per CTA

// Scratch: W transposed to [l][b] layout (256 KB)
__device__ float W_buf[G_SIZE * B_SIZE];

__device__ __forceinline__ float ex2f(float x) {
    float r; asm("ex2.approx.ftz.f32 %0, %1;" : "=f"(r) : "f"(x)); return r;
}
__device__ __forceinline__ unsigned long long pack2(float lo, float hi) {
    unsigned long long r; asm("mov.b64 %0, {%1, %2};" : "=l"(r) : "f"(lo), "f"(hi)); return r;
}
__device__ __forceinline__ void unpack2(unsigned long long v, float &lo, float &hi) {
    asm("mov.b64 {%0, %1}, %2;" : "=f"(lo), "=f"(hi) : "l"(v));
}
__device__ __forceinline__ void fma2(unsigned long long &d, unsigned long long a, unsigned long long b) {
    asm("fma.rn.f32x2 %0, %1, %2, %0;" : "+l"(d) : "l"(a), "l"(b));
}
__device__ __forceinline__ unsigned long long add2(unsigned long long a, unsigned long long b) {
    unsigned long long r; asm("add.rn.f32x2 %0, %1, %2;" : "=l"(r) : "l"(a), "l"(b)); return r;
}
__device__ __forceinline__ unsigned long long mul2(unsigned long long a, unsigned long long b) {
    unsigned long long r; asm("mul.rn.f32x2 %0, %1, %2;" : "=l"(r) : "l"(a), "l"(b)); return r;
}

// Prep: W_buf[l*16+b] = density[b,l] * gw[l]; also writes channel 15 (raw density copy).
__global__ void prep_kernel(const float* __restrict__ density,
                            const float* __restrict__ gw,
                            float* __restrict__ out) {
    int idx = blockIdx.x * blockDim.x + threadIdx.x;  // 65536 = b*4096 + l
    int b = idx >> 12;
    int l = idx & (G_SIZE - 1);
    float d = density[idx];
    W_buf[l * B_SIZE + b] = d * gw[l];
    out[(b * 16 + 15) * G_SIZE + l] = d;
}

// Main: grid = (16 m-tiles, 15 channels), 128 threads.
// Each thread: columns m0 = tile*256 + tid, m1 = m0 + 128; 16 batch accumulators
// per column, packed as f32x2 over (b_even, b_odd) pairs.
__global__ __launch_bounds__(BLOCK) void conv_kernel(const float* __restrict__ xi,
                                                     const float* __restrict__ grid,
                                                     float* __restrict__ out) {
    __shared__ float sW[LCHUNK * B_SIZE];  // 32 KB
    __shared__ float sgl[LCHUNK];          // 2 KB

    const int c = blockIdx.y;
    const int tid = threadIdx.x;
    const int m0 = blockIdx.x * MTILE + tid;
    const int m1 = m0 + BLOCK;

    // xi_t = 1/sigmoid(xi) = 1 + exp(-xi)  (MINVAL=0, MAXVAL=1)
    const float LOG2E = 1.4426950408889634f;
    float xiv = xi[c];
    float xi_t = 1.0f + ex2f(-xiv * LOG2E);
    float c1 = -xi_t * LOG2E;                 // exp(-d^2*xi_t) = ex2(d*(d*c1))
    unsigned long long c1c1 = pack2(c1, c1);

    float gm0 = grid[m0], gm1 = grid[m1];
    unsigned long long ngm = pack2(-gm0, -gm1);

    unsigned long long acc0[8], acc1[8];
#pragma unroll
    for (int p = 0; p < 8; ++p) { acc0[p] = 0ULL; acc1[p] = 0ULL; }

    for (int chunk = 0; chunk < G_SIZE / LCHUNK; ++chunk) {
        __syncthreads();
        // Stage W chunk (512 rows x 16 floats) + grid chunk into smem
        const float4* src = (const float4*)(W_buf + chunk * LCHUNK * B_SIZE);
        float4* dst = (float4*)sW;
#pragma unroll
        for (int i = 0; i < (LCHUNK * B_SIZE / 4) / BLOCK; ++i)  // 16 iters
            dst[tid + i * BLOCK] = src[tid + i * BLOCK];
        if (tid < LCHUNK / 4)
            ((float4*)sgl)[tid] = ((const float4*)(grid + chunk * LCHUNK))[tid];
        __syncthreads();

#pragma unroll 4
        for (int l = 0; l < LCHUNK; ++l) {
            float gl = sgl[l];
            unsigned long long glgl = pack2(gl, gl);
            unsigned long long dd = add2(glgl, ngm);    // (gl-gm0, gl-gm1)
            unsigned long long t  = mul2(dd, c1c1);
            unsigned long long a  = mul2(dd, t);        // (-d^2*xi_t*log2e) x2
            float a0, a1; unpack2(a, a0, a1);
            float e0 = ex2f(a0);
            float e1 = ex2f(a1);
            unsigned long long e00 = pack2(e0, e0);
            unsigned long long e11 = pack2(e1, e1);
            const ulonglong2* wr = (const ulonglong2*)(sW + l * B_SIZE);
#pragma unroll
            for (int q = 0; q < 4; ++q) {
                ulonglong2 w = wr[q];                   // (b4q..b4q+3) as 2 pairs
                fma2(acc0[2 * q],     w.x, e00);
                fma2(acc0[2 * q + 1], w.y, e00);
                fma2(acc1[2 * q],     w.x, e11);
                fma2(acc1[2 * q + 1], w.y, e11);
            }
        }
    }

    float c2 = 0.5f * xi_t;
#pragma unroll
    for (int p = 0; p < 8; ++p) {
        float s0, s1;
        unpack2(acc0[p], s0, s1);
        out[((2 * p) * 16 + c) * G_SIZE + m0]     = s0 * c2;
        out[((2 * p + 1) * 16 + c) * G_SIZE + m0] = s1 * c2;
        unpack2(acc1[p], s0, s1);
        out[((2 * p) * 16 + c) * G_SIZE + m1]     = s0 * c2;
        out[((2 * p + 1) * 16 + c) * G_SIZE + m1] = s1 * c2;
    }
}

extern "C" void kernel_launch(void* const* d_in, const int* in_sizes, int n_in,
                              void* d_out, int out_size) {
    const float* density = (const float*)d_in[0];  // (16,1,4096)
    const float* xi      = (const float*)d_in[1];  // (15,)
    const float* grid    = (const float*)d_in[2];  // (4096,)
    const float* gw      = (const float*)d_in[3];  // (4096,)
    float* out = (float*)d_out;                    // (16,16,4096)

    prep_kernel<<<(B_SIZE * G_SIZE) / 256, 256>>>(density, gw, out);
    conv_kernel<<<dim3(G_SIZE / MTILE, NCH), BLOCK>>>(xi, grid, out);
}

// round 4
// speedup vs baseline: 1.3208x; 1.3208x over previous
#include <cuda_runtime.h>
#include <cuda_bf16.h>

#define G_SIZE 4096
#define B_SIZE 16
#define NCH 15
#define NSPLIT 4
#define LPER (G_SIZE / NSPLIT)   // 1024 per CTA
#define LCHUNK 512
#define BLOCK 128
#define MTILE 256                // 2 columns per thread

// Device scratch (no allocs allowed)
__device__ float W_buf[G_SIZE * B_SIZE];               // W[l][b] = density[b,l]*gw[l]
__device__ float W2_buf[NCH * G_SIZE * B_SIZE];        // W2[c][l][b] = W[l][b]*exp(-gl^2*xi_c)
__device__ float K_buf[NCH * G_SIZE];                  // K[c][l] = 2*xi_c*LOG2E*gl
__device__ float P_buf[NSPLIT * B_SIZE * NCH * G_SIZE];// partials

__device__ __forceinline__ float ex2f(float x) {
    float r; asm("ex2.approx.ftz.f32 %0, %1;" : "=f"(r) : "f"(x)); return r;
}
__device__ __forceinline__ unsigned long long pack2(float lo, float hi) {
    unsigned long long r; asm("mov.b64 %0, {%1, %2};" : "=l"(r) : "f"(lo), "f"(hi)); return r;
}
__device__ __forceinline__ void unpack2(unsigned long long v, float &lo, float &hi) {
    asm("mov.b64 {%0, %1}, %2;" : "=f"(lo), "=f"(hi) : "l"(v));
}
__device__ __forceinline__ void fma2(unsigned long long &d, unsigned long long a, unsigned long long b) {
    asm("fma.rn.f32x2 %0, %1, %2, %0;" : "+l"(d) : "l"(a), "l"(b));
}
__device__ __forceinline__ unsigned long long mul2(unsigned long long a, unsigned long long b) {
    unsigned long long r; asm("mul.rn.f32x2 %0, %1, %2;" : "=l"(r) : "l"(a), "l"(b)); return r;
}

#define LOG2E 1.4426950408889634f

// Prep 1: W[l][b] + raw-density channel-15 copy
__global__ void prep1_kernel(const float* __restrict__ density,
                             const float* __restrict__ gw,
                             float* __restrict__ out) {
    int idx = blockIdx.x * blockDim.x + threadIdx.x;   // b*4096 + l
    int b = idx >> 12;
    int l = idx & (G_SIZE - 1);
    float d = density[idx];
    W_buf[l * B_SIZE + b] = d * gw[l];
    out[(b * 16 + 15) * G_SIZE + l] = d;
}

// Prep 2: per-channel pre-scaled weights W2[c][l][b] and K[c][l]
__global__ void prep2_kernel(const float* __restrict__ xi,
                             const float* __restrict__ grid) {
    int idx = blockIdx.x * blockDim.x + threadIdx.x;   // c*4096 + l  (< 61440)
    int c = idx >> 12;
    int l = idx & (G_SIZE - 1);
    float gl = grid[l];
    float xi_t = 1.0f + ex2f(-xi[c] * LOG2E);          // 1/sigmoid(xi)
    float eg = ex2f(-gl * gl * xi_t * LOG2E);          // exp(-gl^2 * xi_t)
    K_buf[idx] = 2.0f * xi_t * LOG2E * gl;
    const float4* src = (const float4*)(W_buf + l * B_SIZE);
    float4* dst = (float4*)(W2_buf + (size_t)idx * B_SIZE);
#pragma unroll
    for (int q = 0; q < 4; ++q) {
        float4 w = src[q];
        w.x *= eg; w.y *= eg; w.z *= eg; w.w *= eg;
        dst[q] = w;
    }
}

// Main conv: grid (16 m-tiles, 15 channels, 4 L-splits), 128 threads.
__global__ __launch_bounds__(BLOCK) void conv_kernel(const float* __restrict__ xi,
                                                     const float* __restrict__ grid) {
    __shared__ float sW[LCHUNK * B_SIZE];  // 32 KB
    __shared__ float sk[LCHUNK];           // 2 KB

    const int c = blockIdx.y;
    const int split = blockIdx.z;
    const int tid = threadIdx.x;
    const int m0 = blockIdx.x * MTILE + tid;
    const int m1 = m0 + BLOCK;

    float gm0 = grid[m0], gm1 = grid[m1];
    unsigned long long gmgm = pack2(gm0, gm1);

    unsigned long long acc0[8], acc1[8];
#pragma unroll
    for (int p = 0; p < 8; ++p) { acc0[p] = 0ULL; acc1[p] = 0ULL; }

    const int lbase = split * LPER;
    for (int chunk = 0; chunk < LPER / LCHUNK; ++chunk) {
        __syncthreads();
        const int l0 = lbase + chunk * LCHUNK;
        const float4* src = (const float4*)(W2_buf + ((size_t)c * G_SIZE + l0) * B_SIZE);
        float4* dst = (float4*)sW;
#pragma unroll
        for (int i = 0; i < (LCHUNK * B_SIZE / 4) / BLOCK; ++i)   // 16 iters
            dst[tid + i * BLOCK] = src[tid + i * BLOCK];
        if (tid < LCHUNK / 4)
            ((float4*)sk)[tid] = ((const float4*)(K_buf + c * G_SIZE + l0))[tid];
        __syncthreads();

#pragma unroll 4
        for (int l = 0; l < LCHUNK; ++l) {
            float kl = sk[l];
            unsigned long long kk = pack2(kl, kl);
            unsigned long long a = mul2(kk, gmgm);     // (kl*gm0, kl*gm1)
            float a0, a1; unpack2(a, a0, a1);
            float e0 = ex2f(a0);
            float e1 = ex2f(a1);
            unsigned long long e00 = pack2(e0, e0);
            unsigned long long e11 = pack2(e1, e1);
            const ulonglong2* wr = (const ulonglong2*)(sW + l * B_SIZE);
#pragma unroll
            for (int q = 0; q < 4; ++q) {
                ulonglong2 w = wr[q];
                fma2(acc0[2 * q],     w.x, e00);
                fma2(acc0[2 * q + 1], w.y, e00);
                fma2(acc1[2 * q],     w.x, e11);
                fma2(acc1[2 * q + 1], w.y, e11);
            }
        }
    }

    // epilogue scale: 0.5*xi_t*exp(-gm^2*xi_t)
    float xi_t = 1.0f + ex2f(-xi[c] * LOG2E);
    float s0 = 0.5f * xi_t * ex2f(-gm0 * gm0 * xi_t * LOG2E);
    float s1 = 0.5f * xi_t * ex2f(-gm1 * gm1 * xi_t * LOG2E);

    float* P = P_buf + ((size_t)split * B_SIZE * NCH + c) * G_SIZE;
#pragma unroll
    for (int p = 0; p < 8; ++p) {
        float v0, v1;
        unpack2(acc0[p], v0, v1);
        P[(size_t)(2 * p) * NCH * G_SIZE + m0]     = v0 * s0;
        P[(size_t)(2 * p + 1) * NCH * G_SIZE + m0] = v1 * s0;
        unpack2(acc1[p], v0, v1);
        P[(size_t)(2 * p) * NCH * G_SIZE + m1]     = v0 * s1;
        P[(size_t)(2 * p + 1) * NCH * G_SIZE + m1] = v1 * s1;
    }
}

// Reduce the 4 L-split partials into the output (channels 0..14)
__global__ void reduce_kernel(float* __restrict__ out) {
    int idx = blockIdx.x * blockDim.x + threadIdx.x;   // < 16*15*4096
    const int S = B_SIZE * NCH * G_SIZE;
    float s = P_buf[idx] + P_buf[idx + S] + P_buf[idx + 2 * S] + P_buf[idx + 3 * S];
    int cm = idx % (NCH * G_SIZE);
    int b = idx / (NCH * G_SIZE);
    out[b * (16 * G_SIZE) + cm] = s;
}

extern "C" void kernel_launch(void* const* d_in, const int* in_sizes, int n_in,
                              void* d_out, int out_size) {
    const float* density = (const float*)d_in[0];  // (16,1,4096)
    const float* xi      = (const float*)d_in[1];  // (15,)
    const float* grid    = (const float*)d_in[2];  // (4096,)
    const float* gw      = (const float*)d_in[3];  // (4096,)
    float* out = (float*)d_out;                    // (16,16,4096)

    prep1_kernel<<<(B_SIZE * G_SIZE) / 256, 256>>>(density, gw, out);
    prep2_kernel<<<(NCH * G_SIZE) / 128, 128>>>(xi, grid);
    conv_kernel<<<dim3(G_SIZE / MTILE, NCH, NSPLIT), BLOCK>>>(xi, grid);
    reduce_kernel<<<(B_SIZE * NCH * G_SIZE) / 256, 256>>>(out);
}

// round 6
// speedup vs baseline: 10.2559x; 7.7650x over previous
#include <cuda_runtime.h>
#include <cuda_bf16.h>

#define G_SIZE 4096
#define B_SIZE 16
#define NCH 15
#define D_MAX 26          // Taylor degree: terms d = 0..26
#define ND (D_MAX + 1)    // 27

// Device scratch
__device__ float GP_buf[ND * G_SIZE];          // gl^d           (442 KB)
__device__ float F_buf[NCH * G_SIZE];          // gw[l]*exp(-gl^2*xi_c)
__device__ float Mo_buf[NCH * ND * B_SIZE];    // scaled moments

#define LOG2E 1.4426950408889634f

__device__ __forceinline__ float ex2f(float x) {
    float r; asm("ex2.approx.ftz.f32 %0, %1;" : "=f"(r) : "f"(x)); return r;
}

// gl powers: GP[d][l] = gl^d
__global__ void prep_gp_kernel(const float* __restrict__ grid) {
    int l = blockIdx.x * blockDim.x + threadIdx.x;   // < 4096
    float gl = grid[l];
    float p = 1.0f;
#pragma unroll
    for (int d = 0; d < ND; ++d) {
        GP_buf[d * G_SIZE + l] = p;
        p *= gl;
    }
}

// F[c][l] = gw[l] * exp(-gl^2 * xi_t_c)
__global__ void prep_f_kernel(const float* __restrict__ xi,
                              const float* __restrict__ grid,
                              const float* __restrict__ gw) {
    int idx = blockIdx.x * blockDim.x + threadIdx.x;   // < 15*4096
    int c = idx >> 12;
    int l = idx & (G_SIZE - 1);
    float gl = grid[l];
    float xi_t = 1.0f + ex2f(-xi[c] * LOG2E);
    F_buf[idx] = gw[l] * ex2f(-gl * gl * xi_t * LOG2E);
}

// channel 15: raw density copy
__global__ void prep_copy_kernel(const float* __restrict__ density,
                                 float* __restrict__ out) {
    int idx = blockIdx.x * blockDim.x + threadIdx.x;   // b*4096 + l
    int b = idx >> 12;
    int l = idx & (G_SIZE - 1);
    out[(b * 16 + 15) * G_SIZE + l] = density[idx];
}

// Moments: Mo[c][d][b] = (2 xi_t)^d/d! * sum_l density[b,l]*F[c,l]*gl^d
// grid = (9 degree-groups of 3, 15 channels), 256 threads (8 warps, 2 b per warp)
__global__ __launch_bounds__(256) void moments_kernel(const float* __restrict__ xi,
                                                      const float* __restrict__ density) {
    __shared__ __align__(16) float prod[3][G_SIZE];    // 48 KB
    const int dg = blockIdx.x;     // 0..8 -> d = 3*dg + j
    const int c = blockIdx.y;
    const int tid = threadIdx.x;

    const float* F = F_buf + c * G_SIZE;
#pragma unroll
    for (int j = 0; j < 3; ++j) {
        const float* GPr = GP_buf + (3 * dg + j) * G_SIZE;
        for (int i = tid; i < G_SIZE; i += 256)
            prod[j][i] = F[i] * GPr[i];
    }
    __syncthreads();

    const int wid = tid >> 5, lane = tid & 31;

    float xi_t = 1.0f + ex2f(-xi[c] * LOG2E);
    float t = 2.0f * xi_t;
    float coef0 = 1.0f;
    for (int i = 1; i <= 3 * dg; ++i) coef0 = coef0 * t / (float)i;
    float coef1 = coef0 * t / (float)(3 * dg + 1);
    float coef2 = coef1 * t / (float)(3 * dg + 2);

    const float4* p0 = (const float4*)prod[0];
    const float4* p1 = (const float4*)prod[1];
    const float4* p2 = (const float4*)prod[2];

#pragma unroll
    for (int bb = 0; bb < 2; ++bb) {
        int b = 2 * wid + bb;
        const float4* dr = (const float4*)(density + b * G_SIZE);
        float s0 = 0.f, s1 = 0.f, s2 = 0.f;
        float u0 = 0.f, u1 = 0.f, u2 = 0.f;
#pragma unroll 4
        for (int i = lane; i < G_SIZE / 4; i += 32) {
            float4 d4 = dr[i];
            float4 a0 = p0[i], a1 = p1[i], a2 = p2[i];
            s0 += d4.x * a0.x + d4.y * a0.y;
            u0 += d4.z * a0.z + d4.w * a0.w;
            s1 += d4.x * a1.x + d4.y * a1.y;
            u1 += d4.z * a1.z + d4.w * a1.w;
            s2 += d4.x * a2.x + d4.y * a2.y;
            u2 += d4.z * a2.z + d4.w * a2.w;
        }
        s0 += u0; s1 += u1; s2 += u2;
#pragma unroll
        for (int o = 16; o; o >>= 1) {
            s0 += __shfl_xor_sync(0xffffffffu, s0, o);
            s1 += __shfl_xor_sync(0xffffffffu, s1, o);
            s2 += __shfl_xor_sync(0xffffffffu, s2, o);
        }
        if (lane == 0) {
            Mo_buf[(c * ND + 3 * dg + 0) * B_SIZE + b] = s0 * coef0;
            Mo_buf[(c * ND + 3 * dg + 1) * B_SIZE + b] = s1 * coef1;
            Mo_buf[(c * ND + 3 * dg + 2) * B_SIZE + b] = s2 * coef2;
        }
    }
}

// Output: out[b,c,m] = scale_c(gm) * Horner_d( Mo[c][d][b], gm )
// grid = (16 m-blocks, 15 channels), 256 threads, 16 accumulators/thread
__global__ __launch_bounds__(256) void output_kernel(const float* __restrict__ xi,
                                                     const float* __restrict__ grid,
                                                     float* __restrict__ out) {
    __shared__ float sMo[ND * B_SIZE];   // 432 floats
    const int c = blockIdx.y;
    const int m = blockIdx.x * 256 + threadIdx.x;

    for (int i = threadIdx.x; i < ND * B_SIZE; i += 256)
        sMo[i] = Mo_buf[c * ND * B_SIZE + i];
    __syncthreads();

    float gm = grid[m];
    float xi_t = 1.0f + ex2f(-xi[c] * LOG2E);
    float scale = 0.5f * xi_t * ex2f(-gm * gm * xi_t * LOG2E);

    float acc[B_SIZE];
#pragma unroll
    for (int b = 0; b < B_SIZE; ++b)
        acc[b] = sMo[D_MAX * B_SIZE + b];
#pragma unroll
    for (int d = D_MAX - 1; d >= 0; --d) {
#pragma unroll
        for (int b = 0; b < B_SIZE; ++b)
            acc[b] = acc[b] * gm + sMo[d * B_SIZE + b];
    }
#pragma unroll
    for (int b = 0; b < B_SIZE; ++b)
        out[(b * 16 + c) * G_SIZE + m] = acc[b] * scale;
}

extern "C" void kernel_launch(void* const* d_in, const int* in_sizes, int n_in,
                              void* d_out, int out_size) {
    const float* density = (const float*)d_in[0];  // (16,1,4096)
    const float* xi      = (const float*)d_in[1];  // (15,)
    const float* grid    = (const float*)d_in[2];  // (4096,)
    const float* gw      = (const float*)d_in[3];  // (4096,)
    float* out = (float*)d_out;                    // (16,16,4096)

    prep_gp_kernel<<<G_SIZE / 256, 256>>>(grid);
    prep_f_kernel<<<(NCH * G_SIZE) / 256, 256>>>(xi, grid, gw);
    prep_copy_kernel<<<(B_SIZE * G_SIZE) / 256, 256>>>(density, out);
    moments_kernel<<<dim3(9, NCH), 256>>>(xi, density);
    output_kernel<<<dim3(G_SIZE / 256, NCH), 256>>>(xi, grid, out);
}

// round 7
// speedup vs baseline: 13.9924x; 1.3643x over previous
#include <cuda_runtime.h>
#include <cuda_bf16.h>

#define G_SIZE 4096
#define B_SIZE 16
#define NCH 15
#define D_MAX 26          // Taylor degree: terms d = 0..26
#define ND (D_MAX + 1)    // 27
#define NSPL 4
#define LPER (G_SIZE / NSPL)   // 1024

// Device scratch
__device__ float GP_buf[ND * G_SIZE];                   // gl^d
__device__ float F_buf[NCH * G_SIZE];                   // gw[l]*exp(-gl^2*xi_c)
__device__ float Mo_part[NSPL * NCH * ND * B_SIZE];     // split partial moments (coef-scaled)

#define LOG2E 1.4426950408889634f

__device__ __forceinline__ float ex2f(float x) {
    float r; asm("ex2.approx.ftz.f32 %0, %1;" : "=f"(r) : "f"(x)); return r;
}

// Fused prep: F[c][l] for all channels; c==0 threads also write GP powers.
__global__ void prep_kernel(const float* __restrict__ xi,
                            const float* __restrict__ grid,
                            const float* __restrict__ gw) {
    int idx = blockIdx.x * blockDim.x + threadIdx.x;   // < 15*4096
    int c = idx >> 12;
    int l = idx & (G_SIZE - 1);
    float gl = grid[l];
    float xi_t = 1.0f + ex2f(-xi[c] * LOG2E);
    F_buf[idx] = gw[l] * ex2f(-gl * gl * xi_t * LOG2E);
    if (c == 0) {
        float p = 1.0f;
#pragma unroll
        for (int d = 0; d < ND; ++d) {
            GP_buf[d * G_SIZE + l] = p;
            p *= gl;
        }
    }
}

// Moments partials: Mo_part[s][c][d][b] = coef_d * sum_{l in split s} density[b,l]*F[c,l]*gl^d
// grid = (9 degree-groups, 15 channels, 4 l-splits), 256 threads (8 warps x 2 b)
__global__ __launch_bounds__(256) void moments_kernel(const float* __restrict__ xi,
                                                      const float* __restrict__ density) {
    __shared__ __align__(16) float prod[3][LPER];      // 12 KB
    const int dg = blockIdx.x;      // 0..8
    const int c  = blockIdx.y;
    const int sp = blockIdx.z;      // 0..3
    const int tid = threadIdx.x;
    const int l0 = sp * LPER;

    const float* F = F_buf + c * G_SIZE + l0;
    {
        // stage 3 product rows: 3*256 float4 via 256 threads = 3 vec iters
        const float4* f4 = (const float4*)F;
#pragma unroll
        for (int j = 0; j < 3; ++j) {
            const float4* gp4 = (const float4*)(GP_buf + (3 * dg + j) * G_SIZE + l0);
            float4 a = f4[tid];
            float4 g = gp4[tid];
            a.x *= g.x; a.y *= g.y; a.z *= g.z; a.w *= g.w;
            ((float4*)prod[j])[tid] = a;
        }
    }
    __syncthreads();

    const int wid = tid >> 5, lane = tid & 31;

    float xi_t = 1.0f + ex2f(-xi[c] * LOG2E);
    float t = 2.0f * xi_t;
    float coef0 = 1.0f;
    for (int i = 1; i <= 3 * dg; ++i) coef0 = coef0 * t / (float)i;
    float coef1 = coef0 * t / (float)(3 * dg + 1);
    float coef2 = coef1 * t / (float)(3 * dg + 2);

    const float4* p0 = (const float4*)prod[0];
    const float4* p1 = (const float4*)prod[1];
    const float4* p2 = (const float4*)prod[2];

    float* Mo = Mo_part + ((sp * NCH + c) * ND + 3 * dg) * B_SIZE;

#pragma unroll
    for (int bb = 0; bb < 2; ++bb) {
        int b = 2 * wid + bb;
        const float4* dr = (const float4*)(density + b * G_SIZE + l0);
        float s0 = 0.f, s1 = 0.f, s2 = 0.f;
        float u0 = 0.f, u1 = 0.f, u2 = 0.f;
#pragma unroll
        for (int i = 0; i < LPER / 4 / 32; ++i) {      // 8 iters, fully unrolled
            int ix = lane + i * 32;
            float4 d4 = dr[ix];
            float4 a0 = p0[ix], a1 = p1[ix], a2 = p2[ix];
            s0 += d4.x * a0.x + d4.y * a0.y;
            u0 += d4.z * a0.z + d4.w * a0.w;
            s1 += d4.x * a1.x + d4.y * a1.y;
            u1 += d4.z * a1.z + d4.w * a1.w;
            s2 += d4.x * a2.x + d4.y * a2.y;
            u2 += d4.z * a2.z + d4.w * a2.w;
        }
        s0 += u0; s1 += u1; s2 += u2;
#pragma unroll
        for (int o = 16; o; o >>= 1) {
            s0 += __shfl_xor_sync(0xffffffffu, s0, o);
            s1 += __shfl_xor_sync(0xffffffffu, s1, o);
            s2 += __shfl_xor_sync(0xffffffffu, s2, o);
        }
        if (lane == 0) {
            Mo[0 * B_SIZE + b] = s0 * coef0;
            Mo[1 * B_SIZE + b] = s1 * coef1;
            Mo[2 * B_SIZE + b] = s2 * coef2;
        }
    }
}

// Output: channels 0..14 = scale_c(gm) * Horner(sum-of-partials, gm); channel 15 = raw density.
// grid = (16 m-blocks, 16 channels), 256 threads
__global__ __launch_bounds__(256) void output_kernel(const float* __restrict__ xi,
                                                     const float* __restrict__ grid,
                                                     const float* __restrict__ density,
                                                     float* __restrict__ out) {
    const int c = blockIdx.y;
    const int m = blockIdx.x * 256 + threadIdx.x;

    if (c == NCH) {   // raw density channel
#pragma unroll
        for (int b = 0; b < B_SIZE; ++b)
            out[(b * 16 + NCH) * G_SIZE + m] = density[b * G_SIZE + m];
        return;
    }

    __shared__ float sMo[ND * B_SIZE];   // 432 floats
    for (int i = threadIdx.x; i < ND * B_SIZE; i += 256) {
        float s = 0.f;
#pragma unroll
        for (int sp = 0; sp < NSPL; ++sp)
            s += Mo_part[(sp * NCH + c) * ND * B_SIZE + i];
        sMo[i] = s;
    }
    __syncthreads();

    float gm = grid[m];
    float xi_t = 1.0f + ex2f(-xi[c] * LOG2E);
    float scale = 0.5f * xi_t * ex2f(-gm * gm * xi_t * LOG2E);

    float acc[B_SIZE];
#pragma unroll
    for (int b = 0; b < B_SIZE; ++b)
        acc[b] = sMo[D_MAX * B_SIZE + b];
#pragma unroll
    for (int d = D_MAX - 1; d >= 0; --d) {
#pragma unroll
        for (int b = 0; b < B_SIZE; ++b)
            acc[b] = acc[b] * gm + sMo[d * B_SIZE + b];
    }
#pragma unroll
    for (int b = 0; b < B_SIZE; ++b)
        out[(b * 16 + c) * G_SIZE + m] = acc[b] * scale;
}

extern "C" void kernel_launch(void* const* d_in, const int* in_sizes, int n_in,
                              void* d_out, int out_size) {
    const float* density = (const float*)d_in[0];  // (16,1,4096)
    const float* xi      = (const float*)d_in[1];  // (15,)
    const float* grid    = (const float*)d_in[2];  // (4096,)
    const float* gw      = (const float*)d_in[3];  // (4096,)
    float* out = (float*)d_out;                    // (16,16,4096)

    prep_kernel<<<(NCH * G_SIZE) / 256, 256>>>(xi, grid, gw);
    moments_kernel<<<dim3(9, NCH, NSPL), 256>>>(xi, density);
    output_kernel<<<dim3(G_SIZE / 256, NCH + 1), 256>>>(xi, grid, density, out);
}

// round 8
// speedup vs baseline: 15.6229x; 1.1165x over previous
#include <cuda_runtime.h>
#include <cuda_bf16.h>

#define G_SIZE 4096
#define B_SIZE 16
#define NCH 15
#define D_MAX 26          // Taylor degree: terms d = 0..26
#define ND (D_MAX + 1)    // 27
#define NSPL 4
#define LPER (G_SIZE / NSPL)   // 1024

// Device scratch
__device__ float Mo_part[NSPL * NCH * ND * B_SIZE];   // split partial moments (coef-scaled)

#define LOG2E 1.4426950408889634f

__device__ __forceinline__ float ex2f(float x) {
    float r; asm("ex2.approx.ftz.f32 %0, %1;" : "=f"(r) : "f"(x)); return r;
}

// gl^e by binary exponentiation (e uniform across CTA -> no divergence)
__device__ __forceinline__ float powu(float g, int e) {
    float p = 1.0f, b = g;
#pragma unroll
    for (int k = 0; k < 5; ++k) {            // e <= 26 < 32
        if (e & 1) p *= b;
        b *= b;
        e >>= 1;
    }
    return p;
}

// Moments partials, with on-the-fly F/GP generation.
// Mo_part[s][c][d][b] = coef_d * sum_{l in split s} density[b,l] * gw[l]*exp(-gl^2 xi) * gl^d
// grid = (9 degree-groups, 15 channels, 4 l-splits), 256 threads (8 warps x 2 b)
__global__ __launch_bounds__(256) void moments_kernel(const float* __restrict__ xi,
                                                      const float* __restrict__ grid,
                                                      const float* __restrict__ gw,
                                                      const float* __restrict__ density) {
    __shared__ __align__(16) float prod[3][LPER];      // 12 KB
    const int dg = blockIdx.x;      // 0..8 -> degrees 3dg..3dg+2
    const int c  = blockIdx.y;
    const int sp = blockIdx.z;      // 0..3
    const int tid = threadIdx.x;
    const int l0 = sp * LPER;

    const float xi_t = 1.0f + ex2f(-xi[c] * LOG2E);
    const float cg = -xi_t * LOG2E;
    const int e0 = 3 * dg;

    // Stage: each thread builds 4 l-entries for all 3 degree rows
    {
        float4 g4 = ((const float4*)(grid + l0))[tid];
        float4 w4 = ((const float4*)(gw + l0))[tid];
        float4 r0, r1, r2;
        {
            float g = g4.x, F = w4.x * ex2f(g * g * cg), p = powu(g, e0);
            r0.x = F * p; p *= g; r1.x = F * p; p *= g; r2.x = F * p;
        }
        {
            float g = g4.y, F = w4.y * ex2f(g * g * cg), p = powu(g, e0);
            r0.y = F * p; p *= g; r1.y = F * p; p *= g; r2.y = F * p;
        }
        {
            float g = g4.z, F = w4.z * ex2f(g * g * cg), p = powu(g, e0);
            r0.z = F * p; p *= g; r1.z = F * p; p *= g; r2.z = F * p;
        }
        {
            float g = g4.w, F = w4.w * ex2f(g * g * cg), p = powu(g, e0);
            r0.w = F * p; p *= g; r1.w = F * p; p *= g; r2.w = F * p;
        }
        ((float4*)prod[0])[tid] = r0;
        ((float4*)prod[1])[tid] = r1;
        ((float4*)prod[2])[tid] = r2;
    }
    __syncthreads();

    const int wid = tid >> 5, lane = tid & 31;

    float t = 2.0f * xi_t;
    float coef0 = 1.0f;
    for (int i = 1; i <= e0; ++i) coef0 = coef0 * t / (float)i;
    float coef1 = coef0 * t / (float)(e0 + 1);
    float coef2 = coef1 * t / (float)(e0 + 2);

    const float4* p0 = (const float4*)prod[0];
    const float4* p1 = (const float4*)prod[1];
    const float4* p2 = (const float4*)prod[2];

    float* Mo = Mo_part + ((sp * NCH + c) * ND + e0) * B_SIZE;

#pragma unroll
    for (int bb = 0; bb < 2; ++bb) {
        int b = 2 * wid + bb;
        const float4* dr = (const float4*)(density + b * G_SIZE + l0);
        float s0 = 0.f, s1 = 0.f, s2 = 0.f;
        float u0 = 0.f, u1 = 0.f, u2 = 0.f;
#pragma unroll
        for (int i = 0; i < LPER / 4 / 32; ++i) {      // 8 iters, fully unrolled
            int ix = lane + i * 32;
            float4 d4 = dr[ix];
            float4 a0 = p0[ix], a1 = p1[ix], a2 = p2[ix];
            s0 += d4.x * a0.x + d4.y * a0.y;
            u0 += d4.z * a0.z + d4.w * a0.w;
            s1 += d4.x * a1.x + d4.y * a1.y;
            u1 += d4.z * a1.z + d4.w * a1.w;
            s2 += d4.x * a2.x + d4.y * a2.y;
            u2 += d4.z * a2.z + d4.w * a2.w;
        }
        s0 += u0; s1 += u1; s2 += u2;
#pragma unroll
        for (int o = 16; o; o >>= 1) {
            s0 += __shfl_xor_sync(0xffffffffu, s0, o);
            s1 += __shfl_xor_sync(0xffffffffu, s1, o);
            s2 += __shfl_xor_sync(0xffffffffu, s2, o);
        }
        if (lane == 0) {
            Mo[0 * B_SIZE + b] = s0 * coef0;
            Mo[1 * B_SIZE + b] = s1 * coef1;
            Mo[2 * B_SIZE + b] = s2 * coef2;
        }
    }
}

// Output: channels 0..14 = scale_c(gm) * Horner(sum-of-partials, gm); channel 15 = raw density.
// grid = (32 m-blocks, 16 channels), 128 threads
__global__ __launch_bounds__(128) void output_kernel(const float* __restrict__ xi,
                                                     const float* __restrict__ grid,
                                                     const float* __restrict__ density,
                                                     float* __restrict__ out) {
    const int c = blockIdx.y;
    const int m = blockIdx.x * 128 + threadIdx.x;

    if (c == NCH) {   // raw density channel
#pragma unroll
        for (int b = 0; b < B_SIZE; ++b)
            out[(b * 16 + NCH) * G_SIZE + m] = density[b * G_SIZE + m];
        return;
    }

    __shared__ float sMo[ND * B_SIZE];   // 432 floats
    for (int i = threadIdx.x; i < ND * B_SIZE; i += 128) {
        float s = 0.f;
#pragma unroll
        for (int sp = 0; sp < NSPL; ++sp)
            s += Mo_part[(sp * NCH + c) * ND * B_SIZE + i];
        sMo[i] = s;
    }
    __syncthreads();

    float gm = grid[m];
    float xi_t = 1.0f + ex2f(-xi[c] * LOG2E);
    float scale = 0.5f * xi_t * ex2f(-gm * gm * xi_t * LOG2E);

    float acc[B_SIZE];
#pragma unroll
    for (int b = 0; b < B_SIZE; ++b)
        acc[b] = sMo[D_MAX * B_SIZE + b];
#pragma unroll
    for (int d = D_MAX - 1; d >= 0; --d) {
#pragma unroll
        for (int b = 0; b < B_SIZE; ++b)
            acc[b] = acc[b] * gm + sMo[d * B_SIZE + b];
    }
#pragma unroll
    for (int b = 0; b < B_SIZE; ++b)
        out[(b * 16 + c) * G_SIZE + m] = acc[b] * scale;
}

extern "C" void kernel_launch(void* const* d_in, const int* in_sizes, int n_in,
                              void* d_out, int out_size) {
    const float* density = (const float*)d_in[0];  // (16,1,4096)
    const float* xi      = (const float*)d_in[1];  // (15,)
    const float* grid    = (const float*)d_in[2];  // (4096,)
    const float* gw      = (const float*)d_in[3];  // (4096,)
    float* out = (float*)d_out;                    // (16,16,4096)

    moments_kernel<<<dim3(9, NCH, NSPL), 256>>>(xi, grid, gw, density);
    output_kernel<<<dim3(G_SIZE / 128, NCH + 1), 128>>>(xi, grid, density, out);
}